// round 4
// baseline (speedup 1.0000x reference)
#include <cuda_runtime.h>

#define NN 32
#define TTOUT 63
#define TFULL 64
#define DD 64
#define KK 4
#define HH 256
#define SOH 256
#define SS 504      // B*63 slices
#define EE 992

// Scratch (allocation-free rule: __device__ globals)
__device__ float g_Q[SS * KK * NN * HH];     // node[j] @ W1[k][:64]
__device__ float g_P[SS * KK * NN * HH];     // node[i] @ W1[k][64:]
__device__ float g_agg[SS * NN * SOH];       // aggregated messages

// ---------------------------------------------------------------------------
// K1: per-slice node phase: Q,P = X @ W1_split. Grid: 504, Block: 256.
// Static smem: Xs 8KB + Ws 32KB = 40KB.
// ---------------------------------------------------------------------------
__global__ void k1_node(const float* __restrict__ inp, const float* __restrict__ W1) {
    __shared__ float Xs[NN * DD];       // 2048
    __shared__ float Ws[32 * 256];      // 8192 (one 32-row chunk of W1)
    const int tid = threadIdx.x;
    const int s = blockIdx.x;
    const int b = s / TTOUT, t = s - b * TTOUT;

    for (int idx = tid; idx < NN * DD; idx += 256) {
        int n = idx >> 6, d = idx & 63;
        Xs[idx] = inp[((b * NN + n) * TFULL + t) * DD + d];
    }
    const int n  = tid >> 3;
    const int h0 = tid & 7;     // thread owns h = h0 + 8*ii, ii=0..31

    for (int k = 0; k < KK; ++k) {
        // --- Q part: W1 rows [0,64) ---
        float acc[32];
        #pragma unroll
        for (int ii = 0; ii < 32; ++ii) acc[ii] = 0.f;
        for (int ch = 0; ch < 2; ++ch) {
            __syncthreads();
            const float* src = &W1[(k * 128 + ch * 32) * 256];
            for (int idx = tid; idx < 8192; idx += 256) Ws[idx] = src[idx];
            __syncthreads();
            for (int d = 0; d < 32; ++d) {
                float xv = Xs[n * 64 + ch * 32 + d];
                const float* wr = &Ws[d * 256 + h0];
                #pragma unroll
                for (int ii = 0; ii < 32; ++ii) acc[ii] += xv * wr[ii * 8];
            }
        }
        {
            float* qout = &g_Q[((s * KK + k) * NN + n) * HH + h0];
            #pragma unroll
            for (int ii = 0; ii < 32; ++ii) qout[ii * 8] = acc[ii];
        }
        // --- P part: W1 rows [64,128) ---
        #pragma unroll
        for (int ii = 0; ii < 32; ++ii) acc[ii] = 0.f;
        for (int ch = 0; ch < 2; ++ch) {
            __syncthreads();
            const float* src = &W1[(k * 128 + 64 + ch * 32) * 256];
            for (int idx = tid; idx < 8192; idx += 256) Ws[idx] = src[idx];
            __syncthreads();
            for (int d = 0; d < 32; ++d) {
                float xv = Xs[n * 64 + ch * 32 + d];
                const float* wr = &Ws[d * 256 + h0];
                #pragma unroll
                for (int ii = 0; ii < 32; ++ii) acc[ii] += xv * wr[ii * 8];
            }
        }
        {
            float* pout = &g_P[((s * KK + k) * NN + n) * HH + h0];
            #pragma unroll
            for (int ii = 0; ii < 32; ++ii) pout[ii * 8] = acc[ii];
        }
    }
}

// ---------------------------------------------------------------------------
// K2: edge phase. One CTA per (slice, sender i): 31 edges x SO=256,
// loop k=0..3, K-chunks of 32. Grid: 504*32, Block: 256. Static smem 44KB.
// ---------------------------------------------------------------------------
__global__ void k2_edge(const float* __restrict__ W2, const float* __restrict__ b1,
                        const float* __restrict__ b2, const float* __restrict__ rel) {
    __shared__ float h1s[32 * 32];        // [row][h] chunk
    __shared__ float W2s[32 * 256];       // [h][c] chunk
    __shared__ float reds[8 * 256];       // row-group partials

    const int tid = threadIdx.x;
    const int blk = blockIdx.x;
    const int s = blk >> 5, i = blk & 31;
    const int b = s / TTOUT;
    const int tc = tid & 31, tr = tid >> 5;
    const int c0 = tc * 8;                // rows {tr,tr+8,tr+16,tr+24} x cols [c0,c0+8)

    float fused[4][8];
    #pragma unroll
    for (int r = 0; r < 4; ++r)
        #pragma unroll
        for (int c = 0; c < 8; ++c) fused[r][c] = 0.f;

    for (int k = 0; k < KK; ++k) {
        float acc2[4][8];
        #pragma unroll
        for (int r = 0; r < 4; ++r)
            #pragma unroll
            for (int c = 0; c < 8; ++c) acc2[r][c] = 0.f;

        const float* Qk = &g_Q[((s * KK + k) * NN) * HH];
        const float* Pk = &g_P[((s * KK + k) * NN + i) * HH];

        for (int ch = 0; ch < 8; ++ch) {
            const int hh0 = ch * 32;
            __syncthreads();
            // build h1 chunk: rows 0..30 real, row 31 zero
            #pragma unroll
            for (int q = 0; q < 4; ++q) {
                int idx = tid + q * 256;
                int r = idx >> 5, h = idx & 31;
                float v = 0.f;
                if (r < 31) {
                    int j = (r < i) ? r : r + 1;
                    v = Qk[j * HH + hh0 + h] + Pk[hh0 + h] + b1[k * HH + hh0 + h];
                    v = fmaxf(v, 0.f);
                }
                h1s[idx] = v;
            }
            // load W2 chunk (32 x 256) vectorized
            {
                const float4* src = (const float4*)&W2[(k * HH + hh0) * SOH];
                float4* dst = (float4*)W2s;
                #pragma unroll
                for (int q = 0; q < 8; ++q) dst[tid + q * 256] = src[tid + q * 256];
            }
            __syncthreads();
            #pragma unroll
            for (int h = 0; h < 32; ++h) {
                float a0 = h1s[tr * 32 + h];
                float a1 = h1s[(tr + 8) * 32 + h];
                float a2 = h1s[(tr + 16) * 32 + h];
                float a3 = h1s[(tr + 24) * 32 + h];
                float4 w0 = *(const float4*)&W2s[h * 256 + c0];
                float4 w1 = *(const float4*)&W2s[h * 256 + c0 + 4];
                float wv[8] = {w0.x, w0.y, w0.z, w0.w, w1.x, w1.y, w1.z, w1.w};
                #pragma unroll
                for (int cc = 0; cc < 8; ++cc) {
                    acc2[0][cc] += a0 * wv[cc];
                    acc2[1][cc] += a1 * wv[cc];
                    acc2[2][cc] += a2 * wv[cc];
                    acc2[3][cc] += a3 * wv[cc];
                }
            }
        }
        // epilogue for this k: relu(+b2), weight by rel, accumulate
        #pragma unroll
        for (int rr = 0; rr < 4; ++rr) {
            int r = tr + rr * 8;
            float rv = (r < 31) ? rel[(b * EE + i * 31 + r) * KK + k] : 0.f;
            #pragma unroll
            for (int cc = 0; cc < 8; ++cc) {
                float h2 = fmaxf(acc2[rr][cc] + b2[k * SOH + c0 + cc], 0.f);
                fused[rr][cc] += h2 * rv;
            }
        }
    }
    // reduce over the 31 edges (row 31 contributes 0 via rv=0)
    __syncthreads();
    #pragma unroll
    for (int cc = 0; cc < 8; ++cc)
        reds[tr * 256 + c0 + cc] =
            fused[0][cc] + fused[1][cc] + fused[2][cc] + fused[3][cc];
    __syncthreads();
    float sum = 0.f;
    #pragma unroll
    for (int g = 0; g < 8; ++g) sum += reds[g * 256 + tid];
    g_agg[(s * NN + i) * SOH + tid] = sum;
}

// ---------------------------------------------------------------------------
// K3: final node MLP + residual. Grid: 504, Block: 256.
// Static smem: smA 32KB (phased: Xs+aggchunk -> h1 -> h2) + Ws 16KB = 48KB.
// ---------------------------------------------------------------------------
__global__ void k3_final(const float* __restrict__ inp,
                         const float* __restrict__ Wf1, const float* __restrict__ bf1,
                         const float* __restrict__ Wf2, const float* __restrict__ bf2,
                         const float* __restrict__ Wf3, const float* __restrict__ bf3,
                         float* __restrict__ out) {
    __shared__ float smA[8192];     // phase1: [0:2048)=Xs, [2048:2560)=agg chunk
                                    // then: h1 (32x256), then h2 (32x256)
    __shared__ float Ws[4096];      // 16x256 weight chunk (or 64x64 for Wf3)
    const int tid = threadIdx.x;
    const int s = blockIdx.x;
    const int b = s / TTOUT, t = s - b * TTOUT;
    const int n  = tid >> 3;
    const int h0 = tid & 7;

    // load X into smA[0:2048)
    for (int idx = tid; idx < NN * DD; idx += 256) {
        int nn = idx >> 6, d = idx & 63;
        smA[idx] = inp[((b * NN + nn) * TFULL + t) * DD + d];
    }

    // GEMM1: h1 = relu([X | agg] @ Wf1 + bf1), 320 rows chunked by 16
    float acc[32];
    #pragma unroll
    for (int ii = 0; ii < 32; ++ii) acc[ii] = 0.f;
    for (int ch = 0; ch < 20; ++ch) {
        const int r0 = ch * 16;
        __syncthreads();
        {
            const float* src = &Wf1[r0 * 256];
            for (int idx = tid; idx < 4096; idx += 256) Ws[idx] = src[idx];
        }
        if (r0 >= 64) {
            // stage agg columns [r0-64, r0-48) for all 32 nodes: 512 floats
            for (int idx = tid; idx < 512; idx += 256) {
                int nn = idx >> 4, q = idx & 15;
                smA[2048 + idx] = g_agg[(s * NN + nn) * SOH + (r0 - 64) + q];
            }
        }
        __syncthreads();
        if (r0 < 64) {
            for (int d = 0; d < 16; ++d) {
                float xv = smA[n * 64 + r0 + d];
                const float* wr = &Ws[d * 256 + h0];
                #pragma unroll
                for (int ii = 0; ii < 32; ++ii) acc[ii] += xv * wr[ii * 8];
            }
        } else {
            for (int d = 0; d < 16; ++d) {
                float xv = smA[2048 + n * 16 + d];
                const float* wr = &Ws[d * 256 + h0];
                #pragma unroll
                for (int ii = 0; ii < 32; ++ii) acc[ii] += xv * wr[ii * 8];
            }
        }
    }
    __syncthreads();
    #pragma unroll
    for (int ii = 0; ii < 32; ++ii)
        smA[n * 256 + h0 + ii * 8] = fmaxf(acc[ii] + bf1[h0 + ii * 8], 0.f);

    // GEMM2: h2 = relu(h1 @ Wf2 + bf2), 256 rows chunked by 16
    #pragma unroll
    for (int ii = 0; ii < 32; ++ii) acc[ii] = 0.f;
    for (int ch = 0; ch < 16; ++ch) {
        __syncthreads();
        const float* src = &Wf2[ch * 16 * 256];
        for (int idx = tid; idx < 4096; idx += 256) Ws[idx] = src[idx];
        __syncthreads();
        for (int d = 0; d < 16; ++d) {
            float xv = smA[n * 256 + ch * 16 + d];
            const float* wr = &Ws[d * 256 + h0];
            #pragma unroll
            for (int ii = 0; ii < 32; ++ii) acc[ii] += xv * wr[ii * 8];
        }
    }
    __syncthreads();
    #pragma unroll
    for (int ii = 0; ii < 32; ++ii)
        smA[n * 256 + h0 + ii * 8] = fmaxf(acc[ii] + bf2[h0 + ii * 8], 0.f);

    // GEMM3: out = h2 @ Wf3 + bf3 + X, 256 rows chunked by 64 (64x64 tiles)
    const int db = h0 * 8;
    float acc3[8];
    #pragma unroll
    for (int q = 0; q < 8; ++q) acc3[q] = 0.f;
    for (int ch = 0; ch < 4; ++ch) {
        __syncthreads();
        const float* src = &Wf3[ch * 64 * 64];
        for (int idx = tid; idx < 4096; idx += 256) Ws[idx] = src[idx];
        __syncthreads();
        for (int h = 0; h < 64; ++h) {
            float xv = smA[n * 256 + ch * 64 + h];
            const float* wr = &Ws[h * 64 + db];
            #pragma unroll
            for (int q = 0; q < 8; ++q) acc3[q] += xv * wr[q];
        }
    }
    const float* xrow = &inp[((b * NN + n) * TFULL + t) * DD];
    float* orow = &out[((b * NN + n) * TTOUT + t) * DD];
    #pragma unroll
    for (int q = 0; q < 8; ++q) orow[db + q] = acc3[q] + bf3[db + q] + xrow[db + q];
}

// ---------------------------------------------------------------------------
extern "C" void kernel_launch(void* const* d_in, const int* in_sizes, int n_in,
                              void* d_out, int out_size) {
    const float* inp = (const float*)d_in[0];
    const float* rel = (const float*)d_in[1];
    // d_in[2] send_mask, d_in[3] rec_mask: edge structure derived analytically
    const float* W1  = (const float*)d_in[4];
    const float* b1  = (const float*)d_in[5];
    const float* W2  = (const float*)d_in[6];
    const float* b2  = (const float*)d_in[7];
    const float* Wf1 = (const float*)d_in[8];
    const float* bf1 = (const float*)d_in[9];
    const float* Wf2 = (const float*)d_in[10];
    const float* bf2 = (const float*)d_in[11];
    const float* Wf3 = (const float*)d_in[12];
    const float* bf3 = (const float*)d_in[13];
    float* out = (float*)d_out;

    k1_node<<<SS, 256>>>(inp, W1);
    k2_edge<<<SS * NN, 256>>>(W2, b1, b2, rel);
    k3_final<<<SS, 256>>>(inp, Wf1, bf1, Wf2, bf2, Wf3, bf3, out);
}

// round 5
// speedup vs baseline: 5.3293x; 5.3293x over previous
#include <cuda_runtime.h>
#include <cuda_fp16.h>
#include <stdint.h>

#define NN 32
#define TTOUT 63
#define TFULL 64
#define DD 64
#define KK 4
#define HH 256
#define SOH 256
#define SS 504      // B*63 slices
#define EE 992

// Scratch (__device__ globals; no allocation)
__device__ __half g_Qh[SS * KK * NN * HH];    // node[j] @ W1_top           (fp16)
__device__ __half g_Ph[SS * KK * NN * HH];    // node[i] @ W1_bot + b1      (fp16)
__device__ __half g_W2h[KK * HH * SOH];       // W2 in fp16, [k][h][n]
__device__ float  g_agg4[KK * SS * NN * SOH]; // per-k agg partials

// ---------------------------------------------------------------------------
// helpers: ldmatrix / mma
// ---------------------------------------------------------------------------
__device__ __forceinline__ void ldsm_x4(uint32_t& r0, uint32_t& r1, uint32_t& r2,
                                        uint32_t& r3, uint32_t addr) {
    asm volatile("ldmatrix.sync.aligned.m8n8.x4.shared.b16 {%0,%1,%2,%3}, [%4];"
                 : "=r"(r0), "=r"(r1), "=r"(r2), "=r"(r3) : "r"(addr));
}
__device__ __forceinline__ void ldsm_x4_t(uint32_t& r0, uint32_t& r1, uint32_t& r2,
                                          uint32_t& r3, uint32_t addr) {
    asm volatile("ldmatrix.sync.aligned.m8n8.x4.trans.shared.b16 {%0,%1,%2,%3}, [%4];"
                 : "=r"(r0), "=r"(r1), "=r"(r2), "=r"(r3) : "r"(addr));
}
__device__ __forceinline__ void mma16816(float* c, uint32_t a0, uint32_t a1,
                                         uint32_t a2, uint32_t a3,
                                         uint32_t b0, uint32_t b1) {
    asm volatile(
        "mma.sync.aligned.m16n8k16.row.col.f32.f16.f16.f32 "
        "{%0,%1,%2,%3}, {%4,%5,%6,%7}, {%8,%9}, {%0,%1,%2,%3};"
        : "+f"(c[0]), "+f"(c[1]), "+f"(c[2]), "+f"(c[3])
        : "r"(a0), "r"(a1), "r"(a2), "r"(a3), "r"(b0), "r"(b1));
}

// ---------------------------------------------------------------------------
// K0: W2 fp32 -> fp16 (same [k][h][n] layout). Grid 256, Block 256.
// ---------------------------------------------------------------------------
__global__ void k0_w2(const float* __restrict__ W2) {
    int t = blockIdx.x * 256 + threadIdx.x;   // 65536 threads, 1 float4 each
    float4 v = ((const float4*)W2)[t];
    __half2* dst = (__half2*)g_W2h;
    dst[t * 2 + 0] = __floats2half2_rn(v.x, v.y);
    dst[t * 2 + 1] = __floats2half2_rn(v.z, v.w);
}

// ---------------------------------------------------------------------------
// K1: Q,P' = X @ W1_split (+b1 folded into P), fp16 out. Grid (504,4), Block 256.
// ---------------------------------------------------------------------------
__global__ void k1_node(const float* __restrict__ inp, const float* __restrict__ W1,
                        const float* __restrict__ b1) {
    __shared__ float Xs[NN * DD];
    __shared__ float Ws[32 * 256];
    const int tid = threadIdx.x;
    const int s = blockIdx.x, k = blockIdx.y;
    const int b = s / TTOUT, t = s - b * TTOUT;

    for (int idx = tid; idx < NN * DD; idx += 256) {
        int n = idx >> 6, d = idx & 63;
        Xs[idx] = inp[((b * NN + n) * TFULL + t) * DD + d];
    }
    const int n = tid >> 3;
    const int h0 = tid & 7;

    // Q: W1 rows [0,64)
    float acc[32];
    #pragma unroll
    for (int ii = 0; ii < 32; ++ii) acc[ii] = 0.f;
    for (int ch = 0; ch < 2; ++ch) {
        __syncthreads();
        const float* src = &W1[(k * 128 + ch * 32) * 256];
        for (int idx = tid; idx < 8192; idx += 256) Ws[idx] = src[idx];
        __syncthreads();
        for (int d = 0; d < 32; ++d) {
            float xv = Xs[n * 64 + ch * 32 + d];
            const float* wr = &Ws[d * 256 + h0];
            #pragma unroll
            for (int ii = 0; ii < 32; ++ii) acc[ii] += xv * wr[ii * 8];
        }
    }
    {
        __half* qout = &g_Qh[((s * KK + k) * NN + n) * HH + h0];
        #pragma unroll
        for (int ii = 0; ii < 32; ++ii) qout[ii * 8] = __float2half_rn(acc[ii]);
    }
    // P: W1 rows [64,128), + b1
    #pragma unroll
    for (int ii = 0; ii < 32; ++ii) acc[ii] = 0.f;
    for (int ch = 0; ch < 2; ++ch) {
        __syncthreads();
        const float* src = &W1[(k * 128 + 64 + ch * 32) * 256];
        for (int idx = tid; idx < 8192; idx += 256) Ws[idx] = src[idx];
        __syncthreads();
        for (int d = 0; d < 32; ++d) {
            float xv = Xs[n * 64 + ch * 32 + d];
            const float* wr = &Ws[d * 256 + h0];
            #pragma unroll
            for (int ii = 0; ii < 32; ++ii) acc[ii] += xv * wr[ii * 8];
        }
    }
    {
        __half* pout = &g_Ph[((s * KK + k) * NN + n) * HH + h0];
        #pragma unroll
        for (int ii = 0; ii < 32; ++ii)
            pout[ii * 8] = __float2half_rn(acc[ii] + b1[k * HH + h0 + ii * 8]);
    }
}

// ---------------------------------------------------------------------------
// K2: edge GEMM on tensor pipe. CTA = (s, mt, k): M=128 (4 senders x 31 + pad),
// N=256, K=256. Grid 504*8*4, Block 256 (8 warps), dyn smem 192 KB.
// ---------------------------------------------------------------------------
__global__ __launch_bounds__(256, 1)
void k2_edge(const float* __restrict__ rel, const float* __restrict__ b2) {
    extern __shared__ char sm2[];
    __half* As = (__half*)sm2;             // 128 x 256, swizzled, 64 KB
    __half* Bs = (__half*)(sm2 + 65536);   // 256 x 256, swizzled, 128 KB

    const int tid = threadIdx.x;
    const int lane = tid & 31, w = tid >> 5;
    const int cta = blockIdx.x;            // ((s*8 + mt)*4 + k)
    const int k = cta & 3;
    const int mt = (cta >> 2) & 7;
    const int s = cta >> 5;
    const int b = s / TTOUT;

    // ---- stage Bs = W2h[k] (rows h, cols n), 16B-chunk XOR swizzle
    {
        const uint4* src = (const uint4*)(g_W2h + k * HH * SOH);
        #pragma unroll
        for (int it = 0; it < 32; ++it) {
            int cid = it * 256 + tid;
            int row = cid >> 5, ch = cid & 31;
            uint4 v = src[cid];
            *(uint4*)((char*)Bs + row * 512 + (((ch ^ (row & 7))) << 4)) = v;
        }
    }
    // ---- build As = relu(Q[j] + P'[i]); row lr = g*32+r; pad row r==31 zero
    {
        const int lr = tid >> 1;
        const int hh = tid & 1;
        const int g = lr >> 5, r = lr & 31;
        const int isn = mt * 4 + g;
        const bool valid = (r < 31);
        const uint4* qrow = nullptr;
        const uint4* prow = nullptr;
        if (valid) {
            int j = (r < isn) ? r : r + 1;
            qrow = (const uint4*)(g_Qh + ((s * KK + k) * NN + j) * HH);
            prow = (const uint4*)(g_Ph + ((s * KK + k) * NN + isn) * HH);
        }
        const __half2 hz = __floats2half2_rn(0.f, 0.f);
        #pragma unroll
        for (int c = 0; c < 16; ++c) {
            int ch = hh * 16 + c;
            uint4 o;
            if (valid) {
                uint4 q = qrow[ch], p = prow[ch];
                __half2* qh = (__half2*)&q;
                __half2* ph = (__half2*)&p;
                __half2* oh = (__half2*)&o;
                #pragma unroll
                for (int e = 0; e < 4; ++e)
                    oh[e] = __hmax2(__hadd2(qh[e], ph[e]), hz);
            } else {
                o.x = o.y = o.z = o.w = 0u;
            }
            *(uint4*)((char*)As + lr * 512 + (((ch ^ (lr & 7))) << 4)) = o;
        }
    }
    __syncthreads();

    // ---- MMA: warp (wm,wn): rows [wm*32,+32) x cols [wn*128,+128)
    const int wm = w >> 1, wn = w & 1;
    float acc[2][16][4];
    #pragma unroll
    for (int m2 = 0; m2 < 2; ++m2)
        #pragma unroll
        for (int nf = 0; nf < 16; ++nf)
            #pragma unroll
            for (int q = 0; q < 4; ++q) acc[m2][nf][q] = 0.f;

    const uint32_t As_b = (uint32_t)__cvta_generic_to_shared(As);
    const uint32_t Bs_b = (uint32_t)__cvta_generic_to_shared(Bs);
    const int arow = wm * 32 + (lane & 15);
    const uint32_t aaddr0 = As_b + arow * 512;
    const uint32_t aaddr1 = As_b + (arow + 16) * 512;
    const int aswz = arow & 7;                 // (arow+16)&7 == aswz
    const int al16 = lane >> 4;
    const int koff = (lane & 7) + ((lane >> 3) & 1) * 8;
    const int kswz = koff & 7;
    const uint32_t brow0 = Bs_b + koff * 512;
    const int nfb = wn * 16 + (lane >> 4);

    for (int ks = 0; ks < 16; ++ks) {
        uint32_t a0, a1, a2, a3, a4, a5, a6, a7;
        const int chnk = ks * 2 + al16;
        ldsm_x4(a0, a1, a2, a3, aaddr0 + ((chnk ^ aswz) << 4));
        ldsm_x4(a4, a5, a6, a7, aaddr1 + ((chnk ^ aswz) << 4));
        const uint32_t brow = brow0 + ks * 8192;
        #pragma unroll
        for (int nfp = 0; nfp < 8; ++nfp) {
            uint32_t b0, b1v, b2v, b3v;
            const int bch = (nfb + nfp * 2) ^ kswz;
            ldsm_x4_t(b0, b1v, b2v, b3v, brow + (bch << 4));
            mma16816(acc[0][2 * nfp],     a0, a1, a2, a3, b0, b1v);
            mma16816(acc[1][2 * nfp],     a4, a5, a6, a7, b0, b1v);
            mma16816(acc[0][2 * nfp + 1], a0, a1, a2, a3, b2v, b3v);
            mma16816(acc[1][2 * nfp + 1], a4, a5, a6, a7, b2v, b3v);
        }
    }

    // ---- epilogue: h2 = relu(acc + b2) * rel, reduce 32 rows -> per-sender cols
    const int isn = mt * 4 + wm;
    const int r0 = lane >> 2;
    const float* relbase = rel + ((size_t)b * EE + isn * 31) * KK + k;
    float w00 = relbase[r0 * KK];
    float w01 = relbase[(r0 + 8) * KK];
    float w10 = relbase[(r0 + 16) * KK];
    float w11 = (r0 + 24 < 31) ? relbase[(r0 + 24) * KK] : 0.f;
    const float* b2k = b2 + k * SOH;
    float* aggout = g_agg4 + (((size_t)k * SS + s) * NN + isn) * SOH;

    #pragma unroll
    for (int nf = 0; nf < 16; ++nf) {
        int c0 = wn * 128 + nf * 8 + (lane & 3) * 2;
        float bc0 = b2k[c0], bc1 = b2k[c0 + 1];
        float s0 = fmaxf(acc[0][nf][0] + bc0, 0.f) * w00
                 + fmaxf(acc[0][nf][2] + bc0, 0.f) * w01
                 + fmaxf(acc[1][nf][0] + bc0, 0.f) * w10
                 + fmaxf(acc[1][nf][2] + bc0, 0.f) * w11;
        float s1 = fmaxf(acc[0][nf][1] + bc1, 0.f) * w00
                 + fmaxf(acc[0][nf][3] + bc1, 0.f) * w01
                 + fmaxf(acc[1][nf][1] + bc1, 0.f) * w10
                 + fmaxf(acc[1][nf][3] + bc1, 0.f) * w11;
        s0 += __shfl_xor_sync(0xffffffffu, s0, 4);
        s0 += __shfl_xor_sync(0xffffffffu, s0, 8);
        s0 += __shfl_xor_sync(0xffffffffu, s0, 16);
        s1 += __shfl_xor_sync(0xffffffffu, s1, 4);
        s1 += __shfl_xor_sync(0xffffffffu, s1, 8);
        s1 += __shfl_xor_sync(0xffffffffu, s1, 16);
        if (lane < 4) *(float2*)&aggout[c0] = make_float2(s0, s1);
    }
}

// ---------------------------------------------------------------------------
// K3: final node MLP + residual (fp32). Grid 504, Block 256. Static smem 48KB.
// ---------------------------------------------------------------------------
__global__ void k3_final(const float* __restrict__ inp,
                         const float* __restrict__ Wf1, const float* __restrict__ bf1,
                         const float* __restrict__ Wf2, const float* __restrict__ bf2,
                         const float* __restrict__ Wf3, const float* __restrict__ bf3,
                         float* __restrict__ out) {
    __shared__ float smA[8192];
    __shared__ float Ws[4096];
    const int tid = threadIdx.x;
    const int s = blockIdx.x;
    const int b = s / TTOUT, t = s - b * TTOUT;
    const int n = tid >> 3;
    const int h0 = tid & 7;

    for (int idx = tid; idx < NN * DD; idx += 256) {
        int nn = idx >> 6, d = idx & 63;
        smA[idx] = inp[((b * NN + nn) * TFULL + t) * DD + d];
    }

    float acc[32];
    #pragma unroll
    for (int ii = 0; ii < 32; ++ii) acc[ii] = 0.f;
    for (int ch = 0; ch < 20; ++ch) {
        const int r0 = ch * 16;
        __syncthreads();
        {
            const float* src = &Wf1[r0 * 256];
            for (int idx = tid; idx < 4096; idx += 256) Ws[idx] = src[idx];
        }
        if (r0 >= 64) {
            for (int idx = tid; idx < 512; idx += 256) {
                int nn = idx >> 4, q = idx & 15;
                size_t off = ((size_t)s * NN + nn) * SOH + (r0 - 64) + q;
                smA[2048 + idx] = g_agg4[off]
                                + g_agg4[(size_t)SS * NN * SOH + off]
                                + g_agg4[2 * (size_t)SS * NN * SOH + off]
                                + g_agg4[3 * (size_t)SS * NN * SOH + off];
            }
        }
        __syncthreads();
        if (r0 < 64) {
            for (int d = 0; d < 16; ++d) {
                float xv = smA[n * 64 + r0 + d];
                const float* wr = &Ws[d * 256 + h0];
                #pragma unroll
                for (int ii = 0; ii < 32; ++ii) acc[ii] += xv * wr[ii * 8];
            }
        } else {
            for (int d = 0; d < 16; ++d) {
                float xv = smA[2048 + n * 16 + d];
                const float* wr = &Ws[d * 256 + h0];
                #pragma unroll
                for (int ii = 0; ii < 32; ++ii) acc[ii] += xv * wr[ii * 8];
            }
        }
    }
    __syncthreads();
    #pragma unroll
    for (int ii = 0; ii < 32; ++ii)
        smA[n * 256 + h0 + ii * 8] = fmaxf(acc[ii] + bf1[h0 + ii * 8], 0.f);

    #pragma unroll
    for (int ii = 0; ii < 32; ++ii) acc[ii] = 0.f;
    for (int ch = 0; ch < 16; ++ch) {
        __syncthreads();
        const float* src = &Wf2[ch * 16 * 256];
        for (int idx = tid; idx < 4096; idx += 256) Ws[idx] = src[idx];
        __syncthreads();
        for (int d = 0; d < 16; ++d) {
            float xv = smA[n * 256 + ch * 16 + d];
            const float* wr = &Ws[d * 256 + h0];
            #pragma unroll
            for (int ii = 0; ii < 32; ++ii) acc[ii] += xv * wr[ii * 8];
        }
    }
    __syncthreads();
    #pragma unroll
    for (int ii = 0; ii < 32; ++ii)
        smA[n * 256 + h0 + ii * 8] = fmaxf(acc[ii] + bf2[h0 + ii * 8], 0.f);

    const int db = h0 * 8;
    float acc3[8];
    #pragma unroll
    for (int q = 0; q < 8; ++q) acc3[q] = 0.f;
    for (int ch = 0; ch < 4; ++ch) {
        __syncthreads();
        const float* src = &Wf3[ch * 64 * 64];
        for (int idx = tid; idx < 4096; idx += 256) Ws[idx] = src[idx];
        __syncthreads();
        for (int h = 0; h < 64; ++h) {
            float xv = smA[n * 256 + ch * 64 + h];
            const float* wr = &Ws[h * 64 + db];
            #pragma unroll
            for (int q = 0; q < 8; ++q) acc3[q] += xv * wr[q];
        }
    }
    const float* xrow = &inp[((b * NN + n) * TFULL + t) * DD];
    float* orow = &out[((b * NN + n) * TTOUT + t) * DD];
    #pragma unroll
    for (int q = 0; q < 8; ++q) orow[db + q] = acc3[q] + bf3[db + q] + xrow[db + q];
}

// ---------------------------------------------------------------------------
extern "C" void kernel_launch(void* const* d_in, const int* in_sizes, int n_in,
                              void* d_out, int out_size) {
    const float* inp = (const float*)d_in[0];
    const float* rel = (const float*)d_in[1];
    const float* W1  = (const float*)d_in[4];
    const float* b1  = (const float*)d_in[5];
    const float* W2  = (const float*)d_in[6];
    const float* b2  = (const float*)d_in[7];
    const float* Wf1 = (const float*)d_in[8];
    const float* bf1 = (const float*)d_in[9];
    const float* Wf2 = (const float*)d_in[10];
    const float* bf2 = (const float*)d_in[11];
    const float* Wf3 = (const float*)d_in[12];
    const float* bf3 = (const float*)d_in[13];
    float* out = (float*)d_out;

    cudaFuncSetAttribute(k2_edge, cudaFuncAttributeMaxDynamicSharedMemorySize, 196608);

    k0_w2<<<256, 256>>>(W2);
    k1_node<<<dim3(SS, KK), 256>>>(inp, W1, b1);
    k2_edge<<<SS * 8 * 4, 256, 196608>>>(rel, b2);
    k3_final<<<SS, 256>>>(inp, Wf1, bf1, Wf2, bf2, Wf3, bf3, out);
}

// round 6
// speedup vs baseline: 8.9758x; 1.6842x over previous
#include <cuda_runtime.h>
#include <cuda_fp16.h>
#include <stdint.h>

#define NN 32
#define TTOUT 63
#define TFULL 64
#define DD 64
#define KK 4
#define HH 256
#define SOH 256
#define SS 504
#define EE 992
#define MROWS (SS * NN)        // 16128
#define MTILES (MROWS / 128)   // 126

// Scratch (__device__ globals; no allocation)
__device__ __half g_Qh[SS * KK * NN * HH];
__device__ __half g_Ph[SS * KK * NN * HH];
__device__ __half g_W2h[KK * HH * SOH];
__device__ float  g_agg4[KK * SS * NN * SOH];
__device__ __half g_W1h[64 * 2048];        // [d][k*512 + qp*256 + h]
__device__ __half g_Wf1h[320 * 256];
__device__ __half g_Wf2h[256 * 256];
__device__ __half g_Wf3h[256 * 256];       // padded: cols 64..255 zero
__device__ __half g_aug[MROWS * 320];      // [row][0:64)=X, [64:320)=agg

// ---------------------------------------------------------------------------
__device__ __forceinline__ void ldsm_x4(uint32_t& r0, uint32_t& r1, uint32_t& r2,
                                        uint32_t& r3, uint32_t addr) {
    asm volatile("ldmatrix.sync.aligned.m8n8.x4.shared.b16 {%0,%1,%2,%3}, [%4];"
                 : "=r"(r0), "=r"(r1), "=r"(r2), "=r"(r3) : "r"(addr));
}
__device__ __forceinline__ void ldsm_x4_t(uint32_t& r0, uint32_t& r1, uint32_t& r2,
                                          uint32_t& r3, uint32_t addr) {
    asm volatile("ldmatrix.sync.aligned.m8n8.x4.trans.shared.b16 {%0,%1,%2,%3}, [%4];"
                 : "=r"(r0), "=r"(r1), "=r"(r2), "=r"(r3) : "r"(addr));
}
__device__ __forceinline__ void mma16816(float* c, uint32_t a0, uint32_t a1,
                                         uint32_t a2, uint32_t a3,
                                         uint32_t b0, uint32_t b1) {
    asm volatile(
        "mma.sync.aligned.m16n8k16.row.col.f32.f16.f16.f32 "
        "{%0,%1,%2,%3}, {%4,%5,%6,%7}, {%8,%9}, {%0,%1,%2,%3};"
        : "+f"(c[0]), "+f"(c[1]), "+f"(c[2]), "+f"(c[3])
        : "r"(a0), "r"(a1), "r"(a2), "r"(a3), "r"(b0), "r"(b1));
}

// ---------------------------------------------------------------------------
// Converts
// ---------------------------------------------------------------------------
__global__ void c_w2(const float* __restrict__ W2) {
    int t = blockIdx.x * 256 + threadIdx.x;   // 65536
    float4 v = ((const float4*)W2)[t];
    __half2* dst = (__half2*)g_W2h;
    dst[t * 2 + 0] = __floats2half2_rn(v.x, v.y);
    dst[t * 2 + 1] = __floats2half2_rn(v.z, v.w);
}
__global__ void c_w1(const float* __restrict__ W1) {
    int idx = blockIdx.x * 256 + threadIdx.x;  // 131072
    int d = idx >> 11, c = idx & 2047;
    int k = c >> 9, qp = (c >> 8) & 1, h = c & 255;
    g_W1h[idx] = __float2half_rn(W1[(k * 128 + qp * 64 + d) * 256 + h]);
}
__global__ void c_wf(const float* __restrict__ Wf1, const float* __restrict__ Wf2,
                     const float* __restrict__ Wf3) {
    int idx = blockIdx.x * 256 + threadIdx.x;  // 212992
    if (idx < 81920) {
        g_Wf1h[idx] = __float2half_rn(Wf1[idx]);
    } else if (idx < 147456) {
        int i = idx - 81920;
        g_Wf2h[i] = __float2half_rn(Wf2[i]);
    } else {
        int i = idx - 147456;
        int r = i >> 8, c = i & 255;
        g_Wf3h[i] = (c < 64) ? __float2half_rn(Wf3[r * 64 + c]) : __float2half_rn(0.f);
    }
}
__global__ void c_x(const float* __restrict__ inp) {
    int idx = blockIdx.x * 256 + threadIdx.x;  // 1032192
    int gr = idx >> 6, d = idx & 63;
    int s = gr >> 5, n = gr & 31;
    int b = s / TTOUT, t = s - b * TTOUT;
    g_aug[gr * 320 + d] = __float2half_rn(inp[((b * NN + n) * TFULL + t) * DD + d]);
}

// ---------------------------------------------------------------------------
// K1h: Q|P GEMM. M=16128, K=64, N=2048. Grid (126,8), Block 256, smem 48KB.
// ---------------------------------------------------------------------------
__global__ __launch_bounds__(256) void k1h(const float* __restrict__ b1) {
    __shared__ __half As[128 * 64];   // pitch 128B, 8 chunks/row
    __shared__ __half Bs[64 * 256];   // pitch 512B, 32 chunks/row
    const int tid = threadIdx.x, lane = tid & 31, w = tid >> 5;
    const int mtile = blockIdx.x, nt = blockIdx.y;

    {   // stage As: 1024 uint4
        const uint4* src = (const uint4*)g_aug;
        #pragma unroll
        for (int it = 0; it < 4; ++it) {
            int cid = it * 256 + tid; int r = cid >> 3, ch = cid & 7;
            uint4 v = src[(mtile * 128 + r) * 40 + ch];
            *(uint4*)((char*)As + r * 128 + ((ch ^ (r & 7)) << 4)) = v;
        }
    }
    {   // stage Bs: 2048 uint4 (W1h pitch 256 uint4)
        const uint4* src = (const uint4*)g_W1h;
        #pragma unroll
        for (int it = 0; it < 8; ++it) {
            int cid = it * 256 + tid; int r = cid >> 5, ch = cid & 31;
            uint4 v = src[r * 256 + nt * 32 + ch];
            *(uint4*)((char*)Bs + r * 512 + ((ch ^ (r & 7)) << 4)) = v;
        }
    }
    __syncthreads();

    const int wm = w >> 1, wn = w & 1;
    float acc[2][16][4];
    #pragma unroll
    for (int m2 = 0; m2 < 2; ++m2)
        #pragma unroll
        for (int nf = 0; nf < 16; ++nf)
            #pragma unroll
            for (int q = 0; q < 4; ++q) acc[m2][nf][q] = 0.f;

    const uint32_t As_b = (uint32_t)__cvta_generic_to_shared(As);
    const uint32_t Bs_b = (uint32_t)__cvta_generic_to_shared(Bs);
    const int arow = wm * 32 + (lane & 15);
    const int aswz = arow & 7;
    const int al16 = lane >> 4;
    const int koff = (lane & 7) + ((lane >> 3) & 1) * 8;
    const int kswz = koff & 7;
    const uint32_t brow0 = Bs_b + koff * 512;
    const int nfb = wn * 16 + (lane >> 4);

    #pragma unroll
    for (int ks = 0; ks < 4; ++ks) {
        uint32_t a0, a1, a2, a3, a4, a5, a6, a7;
        const int chnk = (ks * 2 + al16) ^ aswz;
        ldsm_x4(a0, a1, a2, a3, As_b + arow * 128 + (chnk << 4));
        ldsm_x4(a4, a5, a6, a7, As_b + (arow + 16) * 128 + (chnk << 4));
        const uint32_t brow = brow0 + ks * 8192;
        #pragma unroll
        for (int nfp = 0; nfp < 8; ++nfp) {
            uint32_t b0, b1v, b2v, b3v;
            ldsm_x4_t(b0, b1v, b2v, b3v, brow + (((nfb + nfp * 2) ^ kswz) << 4));
            mma16816(acc[0][2 * nfp],     a0, a1, a2, a3, b0, b1v);
            mma16816(acc[1][2 * nfp],     a4, a5, a6, a7, b0, b1v);
            mma16816(acc[0][2 * nfp + 1], a0, a1, a2, a3, b2v, b3v);
            mma16816(acc[1][2 * nfp + 1], a4, a5, a6, a7, b2v, b3v);
        }
    }

    const int r0 = lane >> 2;
    #pragma unroll
    for (int nf = 0; nf < 16; ++nf) {
        int C = nt * 256 + wn * 128 + nf * 8 + (lane & 3) * 2;
        int k = C >> 9, qp = (C >> 8) & 1, h = C & 255;
        float bb0 = 0.f, bb1 = 0.f;
        if (qp) { bb0 = b1[k * 256 + h]; bb1 = b1[k * 256 + h + 1]; }
        __half* dst = qp ? g_Ph : g_Qh;
        #pragma unroll
        for (int m2 = 0; m2 < 2; ++m2) {
            int r = wm * 32 + m2 * 16 + r0;
            int gr = mtile * 128 + r;
            int s = gr >> 5, n = gr & 31;
            *(__half2*)&dst[((s * KK + k) * NN + n) * HH + h] =
                __floats2half2_rn(acc[m2][nf][0] + bb0, acc[m2][nf][1] + bb1);
            int gr2 = gr + 8; int s2 = gr2 >> 5, n2 = gr2 & 31;
            *(__half2*)&dst[((s2 * KK + k) * NN + n2) * HH + h] =
                __floats2half2_rn(acc[m2][nf][2] + bb0, acc[m2][nf][3] + bb1);
        }
    }
}

// ---------------------------------------------------------------------------
// K2: persistent edge GEMM. Grid 148, Block 256, dyn smem 192 KB.
// ---------------------------------------------------------------------------
__global__ __launch_bounds__(256, 1)
void k2_edge(const float* __restrict__ rel, const float* __restrict__ b2) {
    extern __shared__ char sm2[];
    __half* As = (__half*)sm2;             // 128 x 256, 64 KB
    __half* Bs = (__half*)(sm2 + 65536);   // 256 x 256, 128 KB

    const int tid = threadIdx.x;
    const int lane = tid & 31, w = tid >> 5;
    const int p = blockIdx.x;
    const int wm = w >> 1, wn = w & 1;

    const uint32_t As_b = (uint32_t)__cvta_generic_to_shared(As);
    const uint32_t Bs_b = (uint32_t)__cvta_generic_to_shared(Bs);
    const int arow = wm * 32 + (lane & 15);
    const uint32_t aaddr0 = As_b + arow * 512;
    const uint32_t aaddr1 = As_b + (arow + 16) * 512;
    const int aswz = arow & 7;
    const int al16 = lane >> 4;
    const int koff = (lane & 7) + ((lane >> 3) & 1) * 8;
    const int kswz = koff & 7;
    const uint32_t brow0 = Bs_b + koff * 512;
    const int nfb = wn * 16 + (lane >> 4);
    const int r0 = lane >> 2;

    for (int k = 0; k < KK; ++k) {
        __syncthreads();
        {   // stage Bs = W2h[k]
            const uint4* src = (const uint4*)(g_W2h + k * HH * SOH);
            #pragma unroll
            for (int it = 0; it < 32; ++it) {
                int cid = it * 256 + tid;
                int row = cid >> 5, ch = cid & 31;
                *(uint4*)((char*)Bs + row * 512 + ((ch ^ (row & 7)) << 4)) = src[cid];
            }
        }
        for (int t = p; t < SS * 8; t += 148) {
            const int s = t >> 3, mt = t & 7;
            const int b = s / TTOUT;
            __syncthreads();
            {   // build As = relu(Q[j] + P'[i])
                const int lr = tid >> 1;
                const int hh = tid & 1;
                const int g = lr >> 5, r = lr & 31;
                const int isn = mt * 4 + g;
                const bool valid = (r < 31);
                const uint4* qrow = nullptr;
                const uint4* prow = nullptr;
                if (valid) {
                    int j = (r < isn) ? r : r + 1;
                    qrow = (const uint4*)(g_Qh + ((s * KK + k) * NN + j) * HH);
                    prow = (const uint4*)(g_Ph + ((s * KK + k) * NN + isn) * HH);
                }
                const __half2 hz = __floats2half2_rn(0.f, 0.f);
                #pragma unroll
                for (int c = 0; c < 16; ++c) {
                    int ch = hh * 16 + c;
                    uint4 o;
                    if (valid) {
                        uint4 q = qrow[ch], pp = prow[ch];
                        __half2* qh = (__half2*)&q;
                        __half2* ph = (__half2*)&pp;
                        __half2* oh = (__half2*)&o;
                        #pragma unroll
                        for (int e = 0; e < 4; ++e)
                            oh[e] = __hmax2(__hadd2(qh[e], ph[e]), hz);
                    } else {
                        o.x = o.y = o.z = o.w = 0u;
                    }
                    *(uint4*)((char*)As + lr * 512 + ((ch ^ (lr & 7)) << 4)) = o;
                }
            }
            __syncthreads();

            float acc[2][16][4];
            #pragma unroll
            for (int m2 = 0; m2 < 2; ++m2)
                #pragma unroll
                for (int nf = 0; nf < 16; ++nf)
                    #pragma unroll
                    for (int q = 0; q < 4; ++q) acc[m2][nf][q] = 0.f;

            for (int ks = 0; ks < 16; ++ks) {
                uint32_t a0, a1, a2, a3, a4, a5, a6, a7;
                const int chnk = (ks * 2 + al16) ^ aswz;
                ldsm_x4(a0, a1, a2, a3, aaddr0 + (chnk << 4));
                ldsm_x4(a4, a5, a6, a7, aaddr1 + (chnk << 4));
                const uint32_t brow = brow0 + ks * 8192;
                #pragma unroll
                for (int nfp = 0; nfp < 8; ++nfp) {
                    uint32_t b0, b1v, b2v, b3v;
                    ldsm_x4_t(b0, b1v, b2v, b3v, brow + (((nfb + nfp * 2) ^ kswz) << 4));
                    mma16816(acc[0][2 * nfp],     a0, a1, a2, a3, b0, b1v);
                    mma16816(acc[1][2 * nfp],     a4, a5, a6, a7, b0, b1v);
                    mma16816(acc[0][2 * nfp + 1], a0, a1, a2, a3, b2v, b3v);
                    mma16816(acc[1][2 * nfp + 1], a4, a5, a6, a7, b2v, b3v);
                }
            }

            // epilogue
            const int isn = mt * 4 + wm;
            const float* relbase = rel + ((size_t)b * EE + isn * 31) * KK + k;
            float w00 = relbase[r0 * KK];
            float w01 = relbase[(r0 + 8) * KK];
            float w10 = relbase[(r0 + 16) * KK];
            float w11 = (r0 + 24 < 31) ? relbase[(r0 + 24) * KK] : 0.f;
            const float* b2k = b2 + k * SOH;
            float* aggout = g_agg4 + (((size_t)k * SS + s) * NN + isn) * SOH;

            #pragma unroll
            for (int nf = 0; nf < 16; ++nf) {
                int c0 = wn * 128 + nf * 8 + (lane & 3) * 2;
                float bc0 = b2k[c0], bc1 = b2k[c0 + 1];
                float s0 = fmaxf(acc[0][nf][0] + bc0, 0.f) * w00
                         + fmaxf(acc[0][nf][2] + bc0, 0.f) * w01
                         + fmaxf(acc[1][nf][0] + bc0, 0.f) * w10
                         + fmaxf(acc[1][nf][2] + bc0, 0.f) * w11;
                float s1 = fmaxf(acc[0][nf][1] + bc1, 0.f) * w00
                         + fmaxf(acc[0][nf][3] + bc1, 0.f) * w01
                         + fmaxf(acc[1][nf][1] + bc1, 0.f) * w10
                         + fmaxf(acc[1][nf][3] + bc1, 0.f) * w11;
                s0 += __shfl_xor_sync(0xffffffffu, s0, 4);
                s0 += __shfl_xor_sync(0xffffffffu, s0, 8);
                s0 += __shfl_xor_sync(0xffffffffu, s0, 16);
                s1 += __shfl_xor_sync(0xffffffffu, s1, 4);
                s1 += __shfl_xor_sync(0xffffffffu, s1, 8);
                s1 += __shfl_xor_sync(0xffffffffu, s1, 16);
                if (lane < 4) *(float2*)&aggout[c0] = make_float2(s0, s1);
            }
        }
    }
}

// ---------------------------------------------------------------------------
// K2b: aug[64:320) = sum_k agg4, fp16. Grid 16128, Block 256.
// ---------------------------------------------------------------------------
__global__ void k2b() {
    int idx = blockIdx.x * 256 + threadIdx.x;
    int gr = idx >> 8, c = idx & 255;
    int s = gr >> 5, n = gr & 31;
    size_t off = ((size_t)s * NN + n) * SOH + c;
    const size_t KS = (size_t)SS * NN * SOH;
    float v = g_agg4[off] + g_agg4[KS + off] + g_agg4[2 * KS + off] + g_agg4[3 * KS + off];
    g_aug[gr * 320 + 64 + c] = __float2half_rn(v);
}

// ---------------------------------------------------------------------------
// K3h: fused 3-layer MLP. Grid 126, Block 256, dyn smem 176 KB.
// ---------------------------------------------------------------------------
__global__ __launch_bounds__(256, 1)
void k3h(const float* __restrict__ bf1, const float* __restrict__ bf2,
         const float* __restrict__ bf3, const float* __restrict__ inp,
         float* __restrict__ out) {
    extern __shared__ char sm3[];
    __half* As = (__half*)sm3;                      // 80 KB: aug tile (pitch 640B); later H2 (pitch 512B)
    __half* Bs = (__half*)(sm3 + 81920);            // 32 KB
    __half* Hs = (__half*)(sm3 + 81920 + 32768);    // 64 KB: H1 (pitch 512B)

    const int tid = threadIdx.x, lane = tid & 31, w = tid >> 5;
    const int wm = w >> 1, wn = w & 1;
    const int mtile = blockIdx.x;

    const uint32_t As_b = (uint32_t)__cvta_generic_to_shared(As);
    const uint32_t Bs_b = (uint32_t)__cvta_generic_to_shared(Bs);
    const uint32_t Hs_b = (uint32_t)__cvta_generic_to_shared(Hs);
    const int arow = wm * 32 + (lane & 15);
    const int aswz = arow & 7;
    const int al16 = lane >> 4;
    const int koff = (lane & 7) + ((lane >> 3) & 1) * 8;
    const int kswz = koff & 7;
    const int nfb = wn * 16 + (lane >> 4);
    const int r0 = lane >> 2;

    // stage As <- aug tile (128 x 40 chunks)
    {
        const uint4* src = (const uint4*)g_aug;
        #pragma unroll
        for (int it = 0; it < 20; ++it) {
            int cid = it * 256 + tid;
            int r = cid / 40, ch = cid % 40;
            *(uint4*)((char*)As + r * 640 + ((ch ^ (r & 7)) << 4)) =
                src[(mtile * 128 + r) * 40 + ch];
        }
    }

    float acc[2][16][4];
    #define ZACC() do { _Pragma("unroll") for (int m2=0;m2<2;++m2) \
        _Pragma("unroll") for (int nf=0;nf<16;++nf) \
        _Pragma("unroll") for (int q=0;q<4;++q) acc[m2][nf][q]=0.f; } while(0)

    // ---- GEMM1: K=320, A pitch 640 ----
    ZACC();
    for (int kc = 0; kc < 5; ++kc) {
        __syncthreads();
        {
            const uint4* src = (const uint4*)g_Wf1h + kc * 2048;
            #pragma unroll
            for (int it = 0; it < 8; ++it) {
                int cid = it * 256 + tid; int rr = cid >> 5, ch = cid & 31;
                *(uint4*)((char*)Bs + rr * 512 + ((ch ^ (rr & 7)) << 4)) = src[cid];
            }
        }
        __syncthreads();
        #pragma unroll
        for (int ki = 0; ki < 4; ++ki) {
            const int chnk = ((kc * 4 + ki) * 2 + al16) ^ aswz;
            uint32_t a0, a1, a2, a3, a4, a5, a6, a7;
            ldsm_x4(a0, a1, a2, a3, As_b + arow * 640 + (chnk << 4));
            ldsm_x4(a4, a5, a6, a7, As_b + (arow + 16) * 640 + (chnk << 4));
            const uint32_t brow = Bs_b + koff * 512 + ki * 8192;
            #pragma unroll
            for (int nfp = 0; nfp < 8; ++nfp) {
                uint32_t b0, b1v, b2v, b3v;
                ldsm_x4_t(b0, b1v, b2v, b3v, brow + (((nfb + nfp * 2) ^ kswz) << 4));
                mma16816(acc[0][2 * nfp],     a0, a1, a2, a3, b0, b1v);
                mma16816(acc[1][2 * nfp],     a4, a5, a6, a7, b0, b1v);
                mma16816(acc[0][2 * nfp + 1], a0, a1, a2, a3, b2v, b3v);
                mma16816(acc[1][2 * nfp + 1], a4, a5, a6, a7, b2v, b3v);
            }
        }
    }
    // epilogue1 -> Hs (relu + bf1)
    #pragma unroll
    for (int nf = 0; nf < 16; ++nf) {
        int c0 = wn * 128 + nf * 8 + (lane & 3) * 2;
        float bb0 = bf1[c0], bb1 = bf1[c0 + 1];
        #pragma unroll
        for (int m2 = 0; m2 < 2; ++m2) {
            int r = wm * 32 + m2 * 16 + r0;
            *(__half2*)((char*)Hs + r * 512 + (((c0 >> 3) ^ (r & 7)) << 4) + (c0 & 7) * 2) =
                __floats2half2_rn(fmaxf(acc[m2][nf][0] + bb0, 0.f),
                                  fmaxf(acc[m2][nf][1] + bb1, 0.f));
            int r2 = r + 8;
            *(__half2*)((char*)Hs + r2 * 512 + (((c0 >> 3) ^ (r2 & 7)) << 4) + (c0 & 7) * 2) =
                __floats2half2_rn(fmaxf(acc[m2][nf][2] + bb0, 0.f),
                                  fmaxf(acc[m2][nf][3] + bb1, 0.f));
        }
    }

    // ---- GEMM2: K=256, A=Hs pitch 512 ----
    ZACC();
    for (int kc = 0; kc < 4; ++kc) {
        __syncthreads();
        {
            const uint4* src = (const uint4*)g_Wf2h + kc * 2048;
            #pragma unroll
            for (int it = 0; it < 8; ++it) {
                int cid = it * 256 + tid; int rr = cid >> 5, ch = cid & 31;
                *(uint4*)((char*)Bs + rr * 512 + ((ch ^ (rr & 7)) << 4)) = src[cid];
            }
        }
        __syncthreads();
        #pragma unroll
        for (int ki = 0; ki < 4; ++ki) {
            const int chnk = ((kc * 4 + ki) * 2 + al16) ^ aswz;
            uint32_t a0, a1, a2, a3, a4, a5, a6, a7;
            ldsm_x4(a0, a1, a2, a3, Hs_b + arow * 512 + (chnk << 4));
            ldsm_x4(a4, a5, a6, a7, Hs_b + (arow + 16) * 512 + (chnk << 4));
            const uint32_t brow = Bs_b + koff * 512 + ki * 8192;
            #pragma unroll
            for (int nfp = 0; nfp < 8; ++nfp) {
                uint32_t b0, b1v, b2v, b3v;
                ldsm_x4_t(b0, b1v, b2v, b3v, brow + (((nfb + nfp * 2) ^ kswz) << 4));
                mma16816(acc[0][2 * nfp],     a0, a1, a2, a3, b0, b1v);
                mma16816(acc[1][2 * nfp],     a4, a5, a6, a7, b0, b1v);
                mma16816(acc[0][2 * nfp + 1], a0, a1, a2, a3, b2v, b3v);
                mma16816(acc[1][2 * nfp + 1], a4, a5, a6, a7, b2v, b3v);
            }
        }
    }
    __syncthreads();
    // epilogue2 -> As region as H2 (relu + bf2), pitch 512
    #pragma unroll
    for (int nf = 0; nf < 16; ++nf) {
        int c0 = wn * 128 + nf * 8 + (lane & 3) * 2;
        float bb0 = bf2[c0], bb1 = bf2[c0 + 1];
        #pragma unroll
        for (int m2 = 0; m2 < 2; ++m2) {
            int r = wm * 32 + m2 * 16 + r0;
            *(__half2*)((char*)As + r * 512 + (((c0 >> 3) ^ (r & 7)) << 4) + (c0 & 7) * 2) =
                __floats2half2_rn(fmaxf(acc[m2][nf][0] + bb0, 0.f),
                                  fmaxf(acc[m2][nf][1] + bb1, 0.f));
            int r2 = r + 8;
            *(__half2*)((char*)As + r2 * 512 + (((c0 >> 3) ^ (r2 & 7)) << 4) + (c0 & 7) * 2) =
                __floats2half2_rn(fmaxf(acc[m2][nf][2] + bb0, 0.f),
                                  fmaxf(acc[m2][nf][3] + bb1, 0.f));
        }
    }

    // ---- GEMM3: K=256, A=As(H2) pitch 512, B=Wf3 padded ----
    ZACC();
    for (int kc = 0; kc < 4; ++kc) {
        __syncthreads();
        {
            const uint4* src = (const uint4*)g_Wf3h + kc * 2048;
            #pragma unroll
            for (int it = 0; it < 8; ++it) {
                int cid = it * 256 + tid; int rr = cid >> 5, ch = cid & 31;
                *(uint4*)((char*)Bs + rr * 512 + ((ch ^ (rr & 7)) << 4)) = src[cid];
            }
        }
        __syncthreads();
        #pragma unroll
        for (int ki = 0; ki < 4; ++ki) {
            const int chnk = ((kc * 4 + ki) * 2 + al16) ^ aswz;
            uint32_t a0, a1, a2, a3, a4, a5, a6, a7;
            ldsm_x4(a0, a1, a2, a3, As_b + arow * 512 + (chnk << 4));
            ldsm_x4(a4, a5, a6, a7, As_b + (arow + 16) * 512 + (chnk << 4));
            const uint32_t brow = Bs_b + koff * 512 + ki * 8192;
            #pragma unroll
            for (int nfp = 0; nfp < 8; ++nfp) {
                uint32_t b0, b1v, b2v, b3v;
                ldsm_x4_t(b0, b1v, b2v, b3v, brow + (((nfb + nfp * 2) ^ kswz) << 4));
                mma16816(acc[0][2 * nfp],     a0, a1, a2, a3, b0, b1v);
                mma16816(acc[1][2 * nfp],     a4, a5, a6, a7, b0, b1v);
                mma16816(acc[0][2 * nfp + 1], a0, a1, a2, a3, b2v, b3v);
                mma16816(acc[1][2 * nfp + 1], a4, a5, a6, a7, b2v, b3v);
            }
        }
    }
    // epilogue3: cols 0..63 only (wn==0, nf<8): + bf3 + residual -> out
    if (wn == 0) {
        #pragma unroll
        for (int nf = 0; nf < 8; ++nf) {
            int c0 = nf * 8 + (lane & 3) * 2;
            float bb0 = bf3[c0], bb1 = bf3[c0 + 1];
            #pragma unroll
            for (int m2 = 0; m2 < 2; ++m2) {
                #pragma unroll
                for (int half = 0; half < 2; ++half) {
                    int r = wm * 32 + m2 * 16 + r0 + half * 8;
                    int gr = mtile * 128 + r;
                    int s = gr >> 5, n = gr & 31;
                    int b = s / TTOUT, t = s - b * TTOUT;
                    size_t xo = ((size_t)(b * NN + n) * TFULL + t) * DD + c0;
                    size_t oo = ((size_t)(b * NN + n) * TTOUT + t) * DD + c0;
                    float2 xv = *(const float2*)&inp[xo];
                    float v0 = acc[m2][nf][half * 2 + 0] + bb0 + xv.x;
                    float v1 = acc[m2][nf][half * 2 + 1] + bb1 + xv.y;
                    *(float2*)&out[oo] = make_float2(v0, v1);
                }
            }
        }
    }
    #undef ZACC
}

// ---------------------------------------------------------------------------
extern "C" void kernel_launch(void* const* d_in, const int* in_sizes, int n_in,
                              void* d_out, int out_size) {
    const float* inp = (const float*)d_in[0];
    const float* rel = (const float*)d_in[1];
    const float* W1  = (const float*)d_in[4];
    const float* b1  = (const float*)d_in[5];
    const float* W2  = (const float*)d_in[6];
    const float* b2  = (const float*)d_in[7];
    const float* Wf1 = (const float*)d_in[8];
    const float* bf1 = (const float*)d_in[9];
    const float* Wf2 = (const float*)d_in[10];
    const float* bf2 = (const float*)d_in[11];
    const float* Wf3 = (const float*)d_in[12];
    const float* bf3 = (const float*)d_in[13];
    float* out = (float*)d_out;

    cudaFuncSetAttribute(k2_edge, cudaFuncAttributeMaxDynamicSharedMemorySize, 196608);
    cudaFuncSetAttribute(k3h, cudaFuncAttributeMaxDynamicSharedMemorySize, 180224);

    c_w2<<<256, 256>>>(W2);
    c_w1<<<512, 256>>>(W1);
    c_wf<<<832, 256>>>(Wf1, Wf2, Wf3);
    c_x<<<4032, 256>>>(inp);
    k1h<<<dim3(MTILES, 8), 256>>>(b1);
    k2_edge<<<148, 256, 196608>>>(rel, b2);
    k2b<<<16128, 256>>>();
    k3h<<<MTILES, 256, 180224>>>(bf1, bf2, bf3, inp, out);
}